// round 9
// baseline (speedup 1.0000x reference)
#include <cuda_runtime.h>
#include <math.h>

// Problem constants (fixed by the dataset)
#define BB 2
#define HH 16
#define NN 8192
#define HD 128
#define NOFF 20

#define FULLMASK 0xffffffffu

// queries per warp (one per 8-lane group)
#define QW 4
// warps per block
#define NWARP 8
// queries per block
#define QB (QW * NWARP)   // 32

__device__ __forceinline__ float dot4_acc(float acc, float4 a, float4 b) {
    acc = fmaf(a.x, b.x, acc);
    acc = fmaf(a.y, b.y, acc);
    acc = fmaf(a.z, b.z, acc);
    acc = fmaf(a.w, b.w, acc);
    return acc;
}

__global__ void __launch_bounds__(256)
dsqg_kernel(const float* __restrict__ q,
            const float* __restrict__ k,
            const float* __restrict__ v,
            const float* __restrict__ pb,   // [J, H]
            const float* __restrict__ se,   // [J, HD]
            float* __restrict__ out)
{
    const int DELTA_C[NOFF] = {1,2,3,4,5,6,7,8,9,11,13,15,16,23,32,64,128,256,512,1024};

    const int lane = threadIdx.x & 31;
    const int s    = lane & 7;        // HD segment: floats [s*16, s*16+16)
    const int g    = lane >> 3;       // query within warp
    const int warp = threadIdx.x >> 5;

    // bh fastest in blockIdx -> concurrent wave covers a narrow n-window over all
    // (b,h): keeps the delta<=1024 reuse window resident in L2.
    const int bh   = blockIdx.x & (BB * HH - 1);
    const int tile = blockIdx.x >> 5;
    const int h    = bh & (HH - 1);
    const int nq   = tile * QB + warp * QW + g;   // this group's query index

    const size_t base = (size_t)bh * ((size_t)NN * HD);
    const int    off  = s * 16;                    // float offset within a row
    const float* qr = q + base + (size_t)nq * HD + off;
    const float* kbase = k + base + off;
    const float* vbase = v + base + off;
    float* orow = out + base + (size_t)nq * HD + off;

    const float sc = 0.08838834764831845f;  // 1/sqrt(128)
    const float NEG_INF = __int_as_float(0xff800000);

    // ---- q segment: 16 floats in registers ----
    float4 qa[4];
#pragma unroll
    for (int i = 0; i < 4; ++i)
        qa[i] = *(const float4*)(qr + i * 4);

    // ================= scores: one 3-shfl reduction per (query, j) =================
    // S[j] = sc * (q . k_{nq-delta_j} + q . se_j) + pb[j,h], or -inf if invalid.
    // Butterfly reduction leaves the result replicated in all 8 lanes of the group,
    // so softmax and the v-weighting below are fully lane-local (no more shuffles).
    float S[NOFF];
#pragma unroll
    for (int j = 0; j < NOFF; ++j) {
        const int row  = nq - DELTA_C[j];
        const int rowc = row < 0 ? 0 : row;
        const float4* kp = (const float4*)(kbase + (size_t)rowc * HD);
        const float4* sp = (const float4*)(se + j * HD + off);
        float p = 0.f;
#pragma unroll
        for (int i = 0; i < 4; ++i) p = dot4_acc(p, qa[i], kp[i]);
#pragma unroll
        for (int i = 0; i < 4; ++i) p = dot4_acc(p, qa[i], sp[i]);
        p += __shfl_xor_sync(FULLMASK, p, 1);
        p += __shfl_xor_sync(FULLMASK, p, 2);
        p += __shfl_xor_sync(FULLMASK, p, 4);
        S[j] = (row >= 0) ? fmaf(sc, p, pb[j * HH + h]) : NEG_INF;
    }

    // ---- softmax over the 20 offsets: pure register math ----
    float mx = S[0];
#pragma unroll
    for (int j = 1; j < NOFF; ++j) mx = fmaxf(mx, S[j]);
    const float ms = (mx == NEG_INF) ? 0.f : mx;
    float P[NOFF];
    float sum = 0.f;
#pragma unroll
    for (int j = 0; j < NOFF; ++j) {
        const float e = __expf(S[j] - ms);   // exp(-inf) -> 0 for invalid offsets
        P[j] = e;
        sum += e;
    }
    const float inv = (sum > 0.f) ? (1.0f / sum) : 0.f;
#pragma unroll
    for (int j = 0; j < NOFF; ++j) P[j] *= inv;

    // ---- output: o += P[j] * v_{nq-delta_j} over this lane's 16-float segment ----
    float4 o[4];
#pragma unroll
    for (int i = 0; i < 4; ++i) { o[i].x = 0.f; o[i].y = 0.f; o[i].z = 0.f; o[i].w = 0.f; }

#pragma unroll
    for (int j = 0; j < NOFF; ++j) {
        const int row  = nq - DELTA_C[j];
        const int rowc = row < 0 ? 0 : row;     // invalid j has P[j] == 0
        const float pj = P[j];
        const float4* vp = (const float4*)(vbase + (size_t)rowc * HD);
#pragma unroll
        for (int i = 0; i < 4; ++i) {
            const float4 v4 = vp[i];
            o[i].x = fmaf(pj, v4.x, o[i].x);
            o[i].y = fmaf(pj, v4.y, o[i].y);
            o[i].z = fmaf(pj, v4.z, o[i].z);
            o[i].w = fmaf(pj, v4.w, o[i].w);
        }
    }

#pragma unroll
    for (int i = 0; i < 4; ++i)
        *(float4*)(orow + i * 4) = o[i];
}

extern "C" void kernel_launch(void* const* d_in, const int* in_sizes, int n_in,
                              void* d_out, int out_size) {
    const float* q  = (const float*)d_in[0];
    const float* k  = (const float*)d_in[1];
    const float* v  = (const float*)d_in[2];
    const float* pb = (const float*)d_in[3];
    const float* se = (const float*)d_in[4];
    float* out = (float*)d_out;

    // 32 queries per block; bh fastest in blockIdx for L2 window locality
    const int nblocks = (BB * HH) * (NN / QB);   // 32 * 256 = 8192
    dsqg_kernel<<<nblocks, 256>>>(q, k, v, pb, se, out);
}

// round 11
// speedup vs baseline: 2.9201x; 2.9201x over previous
#include <cuda_runtime.h>
#include <math.h>

// Problem constants (fixed by the dataset)
#define BB 2
#define HH 16
#define NN 8192
#define HD 128
#define NOFF 20

#define FULLMASK 0xffffffffu

// queries per warp (one per 8-lane group)
#define QW 4
// warps per block
#define NWARP 8
// queries per block
#define QB (QW * NWARP)   // 32

__device__ __forceinline__ float dot4_acc(float acc, float4 a, float4 b) {
    acc = fmaf(a.x, b.x, acc);
    acc = fmaf(a.y, b.y, acc);
    acc = fmaf(a.z, b.z, acc);
    acc = fmaf(a.w, b.w, acc);
    return acc;
}

__global__ void __launch_bounds__(256)
dsqg_kernel(const float* __restrict__ q,
            const float* __restrict__ k,
            const float* __restrict__ v,
            const float* __restrict__ pb,   // [J, H]
            const float* __restrict__ se,   // [J, HD]
            float* __restrict__ out)
{
    const int DELTA_C[NOFF] = {1,2,3,4,5,6,7,8,9,11,13,15,16,23,32,64,128,256,512,1024};

    const int lane = threadIdx.x & 31;
    const int s    = lane & 7;        // position within 8-lane group
    const int g    = lane >> 3;       // query within warp
    const int warp = threadIdx.x >> 5;

    // bh fastest in blockIdx -> concurrent wave covers a narrow n-window over all
    // (b,h): keeps the delta<=1024 reuse window resident in L2.
    const int bh   = blockIdx.x & (BB * HH - 1);
    const int tile = blockIdx.x >> 5;
    const int h    = bh & (HH - 1);
    const int nq   = tile * QB + warp * QW + g;   // this group's query index

    const size_t base = (size_t)bh * ((size_t)NN * HD);
    const float* qr    = q + base + (size_t)nq * HD;
    const float* kbase = k + base;
    const float* vbase = v + base;
    float*       orow  = out + base + (size_t)nq * HD;

    const float sc = 0.08838834764831845f;  // 1/sqrt(128)
    const float NEG_INF = __int_as_float(0xff800000);

    // Contiguous group access: load i covers float4-chunk c = i*8 + s, i.e. the
    // 8 lanes of a group read one dense 128B line per load (4 loads = full row).
    // (R9 used chunk = s*4 + i -> 64B-strided lanes -> 16 L1 wavefronts per LDG.)
#define CHUNK(i) (((i) * 8 + s) * 4)

    // ---- q segment: 16 floats in registers (chunks s, 8+s, 16+s, 24+s) ----
    float4 qa[4];
#pragma unroll
    for (int i = 0; i < 4; ++i)
        qa[i] = *(const float4*)(qr + CHUNK(i));

    // ================= scores: one 3-shfl reduction per (query, j) =================
    // S[j] = sc * (q . k_{nq-delta_j} + q . se_j) + pb[j,h], or -inf if invalid.
    // Butterfly leaves the sum replicated in all 8 lanes of the group, so softmax
    // and the v-weighting below are fully lane-local (no further shuffles).
    float S[NOFF];
#pragma unroll
    for (int j = 0; j < NOFF; ++j) {
        const int row  = nq - DELTA_C[j];
        const int rowc = row < 0 ? 0 : row;
        const float* krow = kbase + (size_t)rowc * HD;
        const float* srow = se + j * HD;
        float p = 0.f;
#pragma unroll
        for (int i = 0; i < 4; ++i) p = dot4_acc(p, qa[i], *(const float4*)(krow + CHUNK(i)));
#pragma unroll
        for (int i = 0; i < 4; ++i) p = dot4_acc(p, qa[i], *(const float4*)(srow + CHUNK(i)));
        p += __shfl_xor_sync(FULLMASK, p, 1);
        p += __shfl_xor_sync(FULLMASK, p, 2);
        p += __shfl_xor_sync(FULLMASK, p, 4);
        S[j] = (row >= 0) ? fmaf(sc, p, pb[j * HH + h]) : NEG_INF;
    }

    // ---- softmax over the 20 offsets: pure register math ----
    float mx = S[0];
#pragma unroll
    for (int j = 1; j < NOFF; ++j) mx = fmaxf(mx, S[j]);
    const float ms = (mx == NEG_INF) ? 0.f : mx;
    float P[NOFF];
    float sum = 0.f;
#pragma unroll
    for (int j = 0; j < NOFF; ++j) {
        const float e = __expf(S[j] - ms);   // exp(-inf) -> 0 for invalid offsets
        P[j] = e;
        sum += e;
    }
    const float inv = (sum > 0.f) ? (1.0f / sum) : 0.f;
#pragma unroll
    for (int j = 0; j < NOFF; ++j) P[j] *= inv;

    // ---- output: o += P[j] * v_{nq-delta_j} over this lane's 4 chunks ----
    float4 o[4];
#pragma unroll
    for (int i = 0; i < 4; ++i) { o[i].x = 0.f; o[i].y = 0.f; o[i].z = 0.f; o[i].w = 0.f; }

#pragma unroll
    for (int j = 0; j < NOFF; ++j) {
        const int row  = nq - DELTA_C[j];
        const int rowc = row < 0 ? 0 : row;     // invalid j has P[j] == 0
        const float pj = P[j];
        const float* vrow = vbase + (size_t)rowc * HD;
#pragma unroll
        for (int i = 0; i < 4; ++i) {
            const float4 v4 = *(const float4*)(vrow + CHUNK(i));
            o[i].x = fmaf(pj, v4.x, o[i].x);
            o[i].y = fmaf(pj, v4.y, o[i].y);
            o[i].z = fmaf(pj, v4.z, o[i].z);
            o[i].w = fmaf(pj, v4.w, o[i].w);
        }
    }

#pragma unroll
    for (int i = 0; i < 4; ++i)
        *(float4*)(orow + CHUNK(i)) = o[i];

#undef CHUNK
}

extern "C" void kernel_launch(void* const* d_in, const int* in_sizes, int n_in,
                              void* d_out, int out_size) {
    const float* q  = (const float*)d_in[0];
    const float* k  = (const float*)d_in[1];
    const float* v  = (const float*)d_in[2];
    const float* pb = (const float*)d_in[3];
    const float* se = (const float*)d_in[4];
    float* out = (float*)d_out;

    // 32 queries per block; bh fastest in blockIdx for L2 window locality
    const int nblocks = (BB * HH) * (NN / QB);   // 32 * 256 = 8192
    dsqg_kernel<<<nblocks, 256>>>(q, k, v, pb, se, out);
}